// round 12
// baseline (speedup 1.0000x reference)
#include <cuda_runtime.h>
#include <cuda_fp16.h>

#define N_NODES 100000
#define N_EDGES 1600000
#define D 128
#define ALPHA 0.5f
#define TILE_NODES 32
#define N_TILES (N_NODES / TILE_NODES)   // 3125 exact
#define WPAD 132
#define SCAN_B 1024
#define SCAN_NB ((N_NODES + SCAN_B - 1) / SCAN_B)   // 98

// -------- static device scratch --------
__device__ __half g_y_src[(size_t)N_NODES * D];  // (x @ (a*Ws)^T)[n]   UNSCALED
__device__ __half g_y_dst[(size_t)N_NODES * D];  // (x @ ((1-a)*Wd)^T)[n]
__device__ int   g_cnt_row[N_NODES], g_cnt_col[N_NODES];
__device__ int   g_off_row[N_NODES], g_off_col[N_NODES];   // block-LOCAL offsets
__device__ int   g_cur_row[N_NODES], g_cur_col[N_NODES];
__device__ int   g_part_row[SCAN_NB], g_part_col[SCAN_NB];
__device__ float g_dinv_out[N_NODES], g_dinv_in[N_NODES];
__device__ int   g_sorted_col[N_EDGES];
__device__ int   g_sorted_row[N_EDGES];
__device__ int   g_is64;

__device__ __forceinline__ int ldidx(const void* p, long long i, int is64) {
  if (is64) return (int)((const long long*)p)[i];
  return ((const int*)p)[i];
}
__device__ __forceinline__ unsigned long long ffma2(
    unsigned long long a, unsigned long long b, unsigned long long c) {
  unsigned long long d;
  asm("fma.rn.f32x2 %0, %1, %2, %3;" : "=l"(d) : "l"(a), "l"(b), "l"(c));
  return d;
}
__device__ __forceinline__ float unpack_sum(unsigned long long a) {
  return __uint_as_float((unsigned)a) + __uint_as_float((unsigned)(a >> 32));
}
__device__ __forceinline__ void cp_async16(void* smem_dst, const void* gsrc) {
  unsigned sa = (unsigned)__cvta_generic_to_shared(smem_dst);
  asm volatile("cp.async.ca.shared.global [%0], [%1], 16;" :: "r"(sa), "l"(gsrc));
}

// -------- B1: zero counts + detect index dtype --------
__global__ void k_prep(const void* ei) {
  long long i = (long long)blockIdx.x * blockDim.x + threadIdx.x;
  if (i == 0) {
    const long long* p = (const long long*)ei;
    int ok = 1;
#pragma unroll
    for (int j = 0; j < 16; j++) {
      long long v = p[j];
      if (v < 0 || v >= N_NODES) ok = 0;
    }
    g_is64 = ok;
  }
  if (i < N_NODES) { g_cnt_row[i] = 0; g_cnt_col[i] = 0; }
}

// -------- B2: degree histograms --------
__global__ void k_hist(const void* ei) {
  long long e = (long long)blockIdx.x * blockDim.x + threadIdx.x;
  if (e >= N_EDGES) return;
  int is64 = g_is64;
  int r = ldidx(ei, e, is64);
  int c = ldidx(ei, (long long)N_EDGES + e, is64);
  atomicAdd(&g_cnt_row[r], 1);
  atomicAdd(&g_cnt_col[c], 1);
}

// -------- B3: blockwise scan; init cursors; compute dinv --------
__global__ void k_scan_blocks() {
  __shared__ int sh[SCAN_B];
  int b = blockIdx.x, t = threadIdx.x;
  int gi = b * SCAN_B + t;

  int v = (gi < N_NODES) ? g_cnt_row[gi] : 0;
  sh[t] = v; __syncthreads();
  for (int o = 1; o < SCAN_B; o <<= 1) {
    int x = (t >= o) ? sh[t - o] : 0;
    __syncthreads(); sh[t] += x; __syncthreads();
  }
  if (gi < N_NODES) {
    g_off_row[gi] = sh[t] - v; g_cur_row[gi] = sh[t] - v;
    g_dinv_out[gi] = v > 0 ? rsqrtf((float)v) : 0.f;
  }
  if (t == SCAN_B - 1) g_part_row[b] = sh[t];
  __syncthreads();

  v = (gi < N_NODES) ? g_cnt_col[gi] : 0;
  sh[t] = v; __syncthreads();
  for (int o = 1; o < SCAN_B; o <<= 1) {
    int x = (t >= o) ? sh[t - o] : 0;
    __syncthreads(); sh[t] += x; __syncthreads();
  }
  if (gi < N_NODES) {
    g_off_col[gi] = sh[t] - v; g_cur_col[gi] = sh[t] - v;
    g_dinv_in[gi] = v > 0 ? rsqrtf((float)v) : 0.f;
  }
  if (t == SCAN_B - 1) g_part_col[b] = sh[t];
}

// -------- B4: exclusive-scan the block totals --------
__global__ void k_scan_tops() {
  __shared__ int sh[128];
  int t = threadIdx.x;
  int v = (t < SCAN_NB) ? g_part_row[t] : 0;
  sh[t] = v; __syncthreads();
  for (int o = 1; o < 128; o <<= 1) {
    int x = (t >= o) ? sh[t - o] : 0;
    __syncthreads(); sh[t] += x; __syncthreads();
  }
  if (t < SCAN_NB) g_part_row[t] = sh[t] - v;
  __syncthreads();
  v = (t < SCAN_NB) ? g_part_col[t] : 0;
  sh[t] = v; __syncthreads();
  for (int o = 1; o < 128; o <<= 1) {
    int x = (t >= o) ? sh[t - o] : 0;
    __syncthreads(); sh[t] += x; __syncthreads();
  }
  if (t < SCAN_NB) g_part_col[t] = sh[t] - v;
}

// -------- B5: build CSR --------
__global__ void k_build(const void* ei) {
  long long e = (long long)blockIdx.x * blockDim.x + threadIdx.x;
  if (e >= N_EDGES) return;
  int is64 = g_is64;
  int r = ldidx(ei, e, is64);
  int c = ldidx(ei, (long long)N_EDGES + e, is64);
  int p = atomicAdd(&g_cur_row[r], 1) + g_part_row[r >> 10];
  g_sorted_col[p] = c;
  int q = atomicAdd(&g_cur_col[c], 1) + g_part_col[c >> 10];
  g_sorted_row[q] = r;
}

// -------- A1: transform — depends ONLY on x, W; fully concurrent with B* ----
__global__ void __launch_bounds__(512, 1) k_transform(
    const float* __restrict__ x,
    const float* __restrict__ W_src,
    const float* __restrict__ W_dst) {
  extern __shared__ float smem[];
  float* Ws = smem;
  float* Wd = Ws + D * WPAD;
  float* xs0 = Wd + D * WPAD;
  float* xs1 = xs0 + TILE_NODES * D;

  int tid = threadIdx.x;
  for (int idx = tid; idx < D * D; idx += 512) {
    int d = idx >> 7, k = idx & 127;
    Ws[d * WPAD + k] = ALPHA * W_src[idx];
    Wd[d * WPAD + k] = (1.f - ALPHA) * W_dst[idx];
  }
  int d = tid & 127;
  int q = tid >> 7;

  const ulonglong2* wsp = (const ulonglong2*)(Ws + d * WPAD);
  const ulonglong2* wdp = (const ulonglong2*)(Wd + d * WPAD);

  {
    long long base = (long long)blockIdx.x * TILE_NODES;
    cp_async16(xs0 + tid * 4, x + base * D + tid * 4);
    cp_async16(xs0 + 2048 + tid * 4, x + base * D + 2048 + tid * 4);
    asm volatile("cp.async.commit_group;");
  }

  int p = 0;
  for (int tile = blockIdx.x; tile < N_TILES; tile += gridDim.x) {
    long long base = (long long)tile * TILE_NODES;
    float* xsr = p ? xs1 : xs0;
    float* xsw = p ? xs0 : xs1;

    asm volatile("cp.async.wait_group 0;");
    __syncthreads();

    int next = tile + gridDim.x;
    if (next < N_TILES) {
      long long nb = (long long)next * TILE_NODES * D;
      cp_async16(xsw + tid * 4, x + nb + tid * 4);
      cp_async16(xsw + 2048 + tid * 4, x + nb + 2048 + tid * 4);
      asm volatile("cp.async.commit_group;");
    }

    unsigned long long acc_s[8], acc_d[8];
#pragma unroll
    for (int i = 0; i < 8; i++) { acc_s[i] = 0ull; acc_d[i] = 0ull; }

    const ulonglong2* xrow = (const ulonglong2*)(xsr + (q * 8) * D);
#pragma unroll 4
    for (int kg = 0; kg < 32; kg++) {
      ulonglong2 ws = wsp[kg];
      ulonglong2 wd = wdp[kg];
#pragma unroll
      for (int i = 0; i < 8; i++) {
        ulonglong2 xv = xrow[i * 32 + kg];
        acc_s[i] = ffma2(xv.x, ws.x, acc_s[i]);
        acc_s[i] = ffma2(xv.y, ws.y, acc_s[i]);
        acc_d[i] = ffma2(xv.x, wd.x, acc_d[i]);
        acc_d[i] = ffma2(xv.y, wd.y, acc_d[i]);
      }
    }

#pragma unroll
    for (int i = 0; i < 8; i++) {
      long long node = base + q * 8 + i;
      g_y_src[node * D + d] = __float2half_rn(unpack_sum(acc_s[i]));
      g_y_dst[node * D + d] = __float2half_rn(unpack_sum(acc_d[i]));
    }
    __syncthreads();
    p ^= 1;
  }
}

// -------- join: gather — per-neighbor dinv applied here --------
__device__ __forceinline__ void acc_row_s(float4& acc, const uint2 v, float s) {
  float2 v0 = __half22float2(*(const __half2*)&v.x);
  float2 v1 = __half22float2(*(const __half2*)&v.y);
  acc.x = fmaf(s, v0.x, acc.x); acc.y = fmaf(s, v0.y, acc.y);
  acc.z = fmaf(s, v1.x, acc.z); acc.w = fmaf(s, v1.y, acc.w);
}

__global__ void __launch_bounds__(256, 4) k_gather(
    float* __restrict__ out,
    const float* __restrict__ b_src, const float* __restrict__ b_dst) {
  int lane = threadIdx.x & 31;
  int node = (blockIdx.x * blockDim.x + threadIdx.x) >> 5;
  if (node >= N_NODES) return;

  float4 accf = make_float4(0.f, 0.f, 0.f, 0.f);
  float4 accb = make_float4(0.f, 0.f, 0.f, 0.f);
  const unsigned FULL = 0xffffffffu;

  // fwd: sum_c dinv_in[c] * y_src[c] over out-neighbors c of node
  {
    int s = g_off_row[node] + g_part_row[node >> 10];
    int cnt = g_cnt_row[node];
    for (int bse = 0; bse < cnt; bse += 32) {
      int n = min(32, cnt - bse);
      int idx = (lane < n) ? g_sorted_col[s + bse + lane] : 0;
      int j = 0;
      for (; j + 4 <= n; j += 4) {
        int i0 = __shfl_sync(FULL, idx, j);
        int i1 = __shfl_sync(FULL, idx, j + 1);
        int i2 = __shfl_sync(FULL, idx, j + 2);
        int i3 = __shfl_sync(FULL, idx, j + 3);
        float s0 = g_dinv_in[i0], s1 = g_dinv_in[i1];   // broadcast, L2-hot
        float s2 = g_dinv_in[i2], s3 = g_dinv_in[i3];
        uint2 v0 = ((const uint2*)g_y_src)[(long long)i0 * 32 + lane];
        uint2 v1 = ((const uint2*)g_y_src)[(long long)i1 * 32 + lane];
        uint2 v2 = ((const uint2*)g_y_src)[(long long)i2 * 32 + lane];
        uint2 v3 = ((const uint2*)g_y_src)[(long long)i3 * 32 + lane];
        acc_row_s(accf, v0, s0); acc_row_s(accf, v1, s1);
        acc_row_s(accf, v2, s2); acc_row_s(accf, v3, s3);
      }
      for (; j < n; j++) {
        int i0 = __shfl_sync(FULL, idx, j);
        float s0 = g_dinv_in[i0];
        uint2 v0 = ((const uint2*)g_y_src)[(long long)i0 * 32 + lane];
        acc_row_s(accf, v0, s0);
      }
    }
  }
  // bwd: sum_r dinv_out[r] * y_dst[r] over in-neighbors r of node
  {
    int s = g_off_col[node] + g_part_col[node >> 10];
    int cnt = g_cnt_col[node];
    for (int bse = 0; bse < cnt; bse += 32) {
      int n = min(32, cnt - bse);
      int idx = (lane < n) ? g_sorted_row[s + bse + lane] : 0;
      int j = 0;
      for (; j + 4 <= n; j += 4) {
        int i0 = __shfl_sync(FULL, idx, j);
        int i1 = __shfl_sync(FULL, idx, j + 1);
        int i2 = __shfl_sync(FULL, idx, j + 2);
        int i3 = __shfl_sync(FULL, idx, j + 3);
        float s0 = g_dinv_out[i0], s1 = g_dinv_out[i1];
        float s2 = g_dinv_out[i2], s3 = g_dinv_out[i3];
        uint2 v0 = ((const uint2*)g_y_dst)[(long long)i0 * 32 + lane];
        uint2 v1 = ((const uint2*)g_y_dst)[(long long)i1 * 32 + lane];
        uint2 v2 = ((const uint2*)g_y_dst)[(long long)i2 * 32 + lane];
        uint2 v3 = ((const uint2*)g_y_dst)[(long long)i3 * 32 + lane];
        acc_row_s(accb, v0, s0); acc_row_s(accb, v1, s1);
        acc_row_s(accb, v2, s2); acc_row_s(accb, v3, s3);
      }
      for (; j < n; j++) {
        int i0 = __shfl_sync(FULL, idx, j);
        float s0 = g_dinv_out[i0];
        uint2 v0 = ((const uint2*)g_y_dst)[(long long)i0 * 32 + lane];
        acc_row_s(accb, v0, s0);
      }
    }
  }

  float dout = g_dinv_out[node];
  float di   = g_dinv_in[node];
  int bidx = lane * 4;
  float4 o;
  o.x = ALPHA * b_src[bidx+0] + (1.f-ALPHA) * b_dst[bidx+0] + dout * accf.x + di * accb.x;
  o.y = ALPHA * b_src[bidx+1] + (1.f-ALPHA) * b_dst[bidx+1] + dout * accf.y + di * accb.y;
  o.z = ALPHA * b_src[bidx+2] + (1.f-ALPHA) * b_dst[bidx+2] + dout * accf.z + di * accb.z;
  o.w = ALPHA * b_src[bidx+3] + (1.f-ALPHA) * b_dst[bidx+3] + dout * accf.w + di * accb.w;
  ((float4*)(out + (long long)node * D))[lane] = o;
}

// -------- launch: transform runs concurrent with the ENTIRE build chain -----
extern "C" void kernel_launch(void* const* d_in, const int* in_sizes, int n_in,
                              void* d_out, int out_size) {
  const float* x     = (const float*)d_in[0];
  const void*  ei    = d_in[1];
  const float* W_src = (const float*)d_in[2];
  const float* b_src = (const float*)d_in[3];
  const float* W_dst = (const float*)d_in[4];
  const float* b_dst = (const float*)d_in[5];
  float* out = (float*)d_out;

  cudaStream_t s2;
  cudaStreamCreateWithFlags(&s2, cudaStreamNonBlocking);
  cudaEvent_t evFork, evJoin;
  cudaEventCreateWithFlags(&evFork, cudaEventDisableTiming);
  cudaEventCreateWithFlags(&evJoin, cudaEventDisableTiming);

  // fork at t=0: whole preprocessing chain on s2
  cudaEventRecord(evFork, 0);
  cudaStreamWaitEvent(s2, evFork, 0);
  k_prep<<<(N_NODES + 255) / 256, 256, 0, s2>>>(ei);
  k_hist<<<(N_EDGES + 255) / 256, 256, 0, s2>>>(ei);
  k_scan_blocks<<<SCAN_NB, SCAN_B, 0, s2>>>();
  k_scan_tops<<<1, 128, 0, s2>>>();
  k_build<<<(N_EDGES + 255) / 256, 256, 0, s2>>>(ei);
  cudaEventRecord(evJoin, s2);

  // transform on main stream, no dependencies
  size_t smem_bytes = (size_t)(2 * D * WPAD + 2 * TILE_NODES * D) * sizeof(float);
  cudaFuncSetAttribute(k_transform, cudaFuncAttributeMaxDynamicSharedMemorySize,
                       (int)smem_bytes);
  k_transform<<<152, 512, smem_bytes>>>(x, W_src, W_dst);

  // join: gather needs y (main) + CSR/dinv (s2)
  cudaStreamWaitEvent(0, evJoin, 0);
  k_gather<<<(N_NODES * 32 + 255) / 256, 256>>>(out, b_src, b_dst);
}

// round 13
// speedup vs baseline: 1.4074x; 1.4074x over previous
#include <cuda_runtime.h>
#include <cuda_fp16.h>

#define N_NODES 100000
#define N_EDGES 1600000
#define D 128
#define ALPHA 0.5f
#define TILE_NODES 32
#define N_TILES (N_NODES / TILE_NODES)   // 3125 exact
#define NSTR 264                          // W smem stride (words): conflict-free B frags
#define XSTR 132                          // x smem stride (words): conflict-free A frags
#define SCAN_B 1024
#define SCAN_NB ((N_NODES + SCAN_B - 1) / SCAN_B)   // 98

// -------- static device scratch --------
__device__ __half g_y_src[(size_t)N_NODES * D];  // dinv_in[n] * (x @ (a*Ws)^T)[n]
__device__ __half g_y_dst[(size_t)N_NODES * D];  // dinv_out[n] * (x @ ((1-a)*Wd)^T)[n]
__device__ int   g_cnt_row[N_NODES], g_cnt_col[N_NODES];
__device__ int   g_off_row[N_NODES], g_off_col[N_NODES];   // block-LOCAL offsets
__device__ int   g_cur_row[N_NODES], g_cur_col[N_NODES];
__device__ int   g_part_row[SCAN_NB], g_part_col[SCAN_NB];
__device__ float g_dinv_out[N_NODES], g_dinv_in[N_NODES];
__device__ int   g_sorted_col[N_EDGES];
__device__ int   g_sorted_row[N_EDGES];
__device__ int   g_is64;

__device__ __forceinline__ int ldidx(const void* p, long long i, int is64) {
  if (is64) return (int)((const long long*)p)[i];
  return ((const int*)p)[i];
}
__device__ __forceinline__ void cp_async16(void* smem_dst, const void* gsrc) {
  unsigned sa = (unsigned)__cvta_generic_to_shared(smem_dst);
  asm volatile("cp.async.ca.shared.global [%0], [%1], 16;" :: "r"(sa), "l"(gsrc));
}
__device__ __forceinline__ unsigned f2tf32(float f) {
  unsigned t; asm("cvt.rna.tf32.f32 %0, %1;" : "=r"(t) : "f"(f));
  return t;
}
__device__ __forceinline__ void mma_tf32(float* c, unsigned a0, unsigned a1,
                                         unsigned a2, unsigned a3,
                                         unsigned b0, unsigned b1) {
  asm volatile(
    "mma.sync.aligned.m16n8k8.row.col.f32.tf32.tf32.f32 "
    "{%0,%1,%2,%3}, {%4,%5,%6,%7}, {%8,%9}, {%0,%1,%2,%3};"
    : "+f"(c[0]), "+f"(c[1]), "+f"(c[2]), "+f"(c[3])
    : "r"(a0), "r"(a1), "r"(a2), "r"(a3), "r"(b0), "r"(b1));
}

// -------- 1: zero counts + detect index dtype --------
__global__ void k_prep(const void* ei) {
  long long i = (long long)blockIdx.x * blockDim.x + threadIdx.x;
  if (i == 0) {
    const long long* p = (const long long*)ei;
    int ok = 1;
#pragma unroll
    for (int j = 0; j < 16; j++) {
      long long v = p[j];
      if (v < 0 || v >= N_NODES) ok = 0;
    }
    g_is64 = ok;
  }
  if (i < N_NODES) { g_cnt_row[i] = 0; g_cnt_col[i] = 0; }
}

// -------- 2: degree histograms --------
__global__ void k_hist(const void* ei) {
  long long e = (long long)blockIdx.x * blockDim.x + threadIdx.x;
  if (e >= N_EDGES) return;
  int is64 = g_is64;
  int r = ldidx(ei, e, is64);
  int c = ldidx(ei, (long long)N_EDGES + e, is64);
  atomicAdd(&g_cnt_row[r], 1);
  atomicAdd(&g_cnt_col[c], 1);
}

// -------- B: blockwise scan; init cursors; compute dinv (on stream 2) --------
__global__ void k_scan_blocks() {
  __shared__ int sh[SCAN_B];
  int b = blockIdx.x, t = threadIdx.x;
  int gi = b * SCAN_B + t;

  int v = (gi < N_NODES) ? g_cnt_row[gi] : 0;
  sh[t] = v; __syncthreads();
  for (int o = 1; o < SCAN_B; o <<= 1) {
    int x = (t >= o) ? sh[t - o] : 0;
    __syncthreads(); sh[t] += x; __syncthreads();
  }
  if (gi < N_NODES) {
    g_off_row[gi] = sh[t] - v; g_cur_row[gi] = sh[t] - v;
    g_dinv_out[gi] = v > 0 ? rsqrtf((float)v) : 0.f;
  }
  if (t == SCAN_B - 1) g_part_row[b] = sh[t];
  __syncthreads();

  v = (gi < N_NODES) ? g_cnt_col[gi] : 0;
  sh[t] = v; __syncthreads();
  for (int o = 1; o < SCAN_B; o <<= 1) {
    int x = (t >= o) ? sh[t - o] : 0;
    __syncthreads(); sh[t] += x; __syncthreads();
  }
  if (gi < N_NODES) {
    g_off_col[gi] = sh[t] - v; g_cur_col[gi] = sh[t] - v;
    g_dinv_in[gi] = v > 0 ? rsqrtf((float)v) : 0.f;
  }
  if (t == SCAN_B - 1) g_part_col[b] = sh[t];
}

__global__ void k_scan_tops() {
  __shared__ int sh[128];
  int t = threadIdx.x;
  int v = (t < SCAN_NB) ? g_part_row[t] : 0;
  sh[t] = v; __syncthreads();
  for (int o = 1; o < 128; o <<= 1) {
    int x = (t >= o) ? sh[t - o] : 0;
    __syncthreads(); sh[t] += x; __syncthreads();
  }
  if (t < SCAN_NB) g_part_row[t] = sh[t] - v;
  __syncthreads();
  v = (t < SCAN_NB) ? g_part_col[t] : 0;
  sh[t] = v; __syncthreads();
  for (int o = 1; o < 128; o <<= 1) {
    int x = (t >= o) ? sh[t - o] : 0;
    __syncthreads(); sh[t] += x; __syncthreads();
  }
  if (t < SCAN_NB) g_part_col[t] = sh[t] - v;
}

__global__ void k_build(const void* ei) {
  long long e = (long long)blockIdx.x * blockDim.x + threadIdx.x;
  if (e >= N_EDGES) return;
  int is64 = g_is64;
  int r = ldidx(ei, e, is64);
  int c = ldidx(ei, (long long)N_EDGES + e, is64);
  int p = atomicAdd(&g_cur_row[r], 1) + g_part_row[r >> 10];
  g_sorted_col[p] = c;
  int q = atomicAdd(&g_cur_col[c], 1) + g_part_col[c >> 10];
  g_sorted_row[q] = r;
}

// -------- transform: mma.sync tf32 tensor-core GEMM, fp16 prescaled y -------
// Block: 256 thr = 8 warps. Tile: 32 nodes x 256 outputs (y_src 128 | y_dst 128).
// Warp (wm, wn): wm = wid&1 -> 16 rows; wn = wid>>1 -> 64 cols (8 n-tiles of 8).
__global__ void __launch_bounds__(256, 1) k_transform(
    const float* __restrict__ x,
    const float* __restrict__ W_src,
    const float* __restrict__ W_dst) {
  extern __shared__ float smem[];
  float* Wsm = smem;                        // [128 k][NSTR] tf32 bits, cols 0-127=aWs, 128-255=(1-a)Wd
  float* xs0 = Wsm + 128 * NSTR;            // [32][XSTR]
  float* xs1 = xs0 + TILE_NODES * XSTR;

  int tid = threadIdx.x;
  // fill W transposed to [k][n], pre-truncated to tf32 (one-time; L2-hot after block 0)
  for (int idx = tid; idx < 128 * 256; idx += 256) {
    int k = idx >> 8, n = idx & 255;
    float w = (n < 128) ? ALPHA * W_src[n * 128 + k]
                        : (1.f - ALPHA) * W_dst[(n - 128) * 128 + k];
    Wsm[k * NSTR + n] = __uint_as_float(f2tf32(w));
  }

  int lane = tid & 31, wid = tid >> 5;
  int g = lane >> 2, tig = lane & 3;        // groupID, thread-in-group
  int wm = wid & 1, wn = wid >> 1;

  // prologue: stage first tile (32 rows x 128 floats -> stride-XSTR smem)
  {
    long long base = (long long)blockIdx.x * TILE_NODES;
    for (int i = tid; i < TILE_NODES * 32; i += 256) {       // 1024 16B chunks
      int row = i >> 5, ch = i & 31;
      cp_async16(xs0 + row * XSTR + ch * 4, x + (base + row) * D + ch * 4);
    }
    asm volatile("cp.async.commit_group;");
  }

  int pp = 0;
  for (int tile = blockIdx.x; tile < N_TILES; tile += gridDim.x) {
    long long base = (long long)tile * TILE_NODES;
    float* xsr = pp ? xs1 : xs0;
    float* xsw = pp ? xs0 : xs1;

    asm volatile("cp.async.wait_group 0;");
    __syncthreads();                         // tile ready; prev reads done

    int next = tile + gridDim.x;
    if (next < N_TILES) {
      long long nb = (long long)next * TILE_NODES;
      for (int i = tid; i < TILE_NODES * 32; i += 256) {
        int row = i >> 5, ch = i & 31;
        cp_async16(xsw + row * XSTR + ch * 4, x + (nb + row) * D + ch * 4);
      }
      asm volatile("cp.async.commit_group;");
    }

    float c[8][4];
#pragma unroll
    for (int nt = 0; nt < 8; nt++) { c[nt][0]=0.f; c[nt][1]=0.f; c[nt][2]=0.f; c[nt][3]=0.f; }

#pragma unroll
    for (int ks = 0; ks < 16; ks++) {
      int k0 = ks * 8;
      const float* ab = xsr + (wm * 16 + g) * XSTR + k0 + tig;
      unsigned a0 = f2tf32(ab[0]);
      unsigned a1 = f2tf32(ab[8 * XSTR]);
      unsigned a2 = f2tf32(ab[4]);
      unsigned a3 = f2tf32(ab[8 * XSTR + 4]);
      const float* bb = Wsm + (k0 + tig) * NSTR + wn * 64 + g;
#pragma unroll
      for (int nt = 0; nt < 8; nt++) {
        unsigned b0 = __float_as_uint(bb[nt * 8]);
        unsigned b1 = __float_as_uint(bb[nt * 8 + 4 * NSTR]);
        mma_tf32(c[nt], a0, a1, a2, a3, b0, b1);
      }
    }

    // epilogue: prescale by dinv, convert fp16, store
    {
      int r0 = wm * 16 + g, r1 = r0 + 8;
      long long n0 = base + r0, n1 = base + r1;
      float s0, s1;
      __half* ybase;
      if (wn < 2) {                          // y_src: scale = dinv_in (col degree)
        int c0 = g_cnt_col[n0], c1 = g_cnt_col[n1];
        s0 = c0 > 0 ? rsqrtf((float)c0) : 0.f;
        s1 = c1 > 0 ? rsqrtf((float)c1) : 0.f;
        ybase = g_y_src;
      } else {                               // y_dst: scale = dinv_out (row degree)
        int c0 = g_cnt_row[n0], c1 = g_cnt_row[n1];
        s0 = c0 > 0 ? rsqrtf((float)c0) : 0.f;
        s1 = c1 > 0 ? rsqrtf((float)c1) : 0.f;
        ybase = g_y_dst;
      }
      int cb = (wn & 1) * 64 + tig * 2;
#pragma unroll
      for (int nt = 0; nt < 8; nt++) {
        __half2 h0 = __floats2half2_rn(s0 * c[nt][0], s0 * c[nt][1]);
        *(__half2*)(ybase + n0 * D + cb + nt * 8) = h0;
        __half2 h1 = __floats2half2_rn(s1 * c[nt][2], s1 * c[nt][3]);
        *(__half2*)(ybase + n1 * D + cb + nt * 8) = h1;
      }
    }
    pp ^= 1;
  }
}

// -------- gather — warp per node, 4-way MLP, single out write (R11) --------
__device__ __forceinline__ void acc_row(float4& acc, const uint2 v) {
  float2 v0 = __half22float2(*(const __half2*)&v.x);
  float2 v1 = __half22float2(*(const __half2*)&v.y);
  acc.x += v0.x; acc.y += v0.y; acc.z += v1.x; acc.w += v1.y;
}

__global__ void __launch_bounds__(256, 4) k_gather(
    float* __restrict__ out,
    const float* __restrict__ b_src, const float* __restrict__ b_dst) {
  int lane = threadIdx.x & 31;
  int node = (blockIdx.x * blockDim.x + threadIdx.x) >> 5;
  if (node >= N_NODES) return;

  float4 accf = make_float4(0.f, 0.f, 0.f, 0.f);
  float4 accb = make_float4(0.f, 0.f, 0.f, 0.f);
  const unsigned FULL = 0xffffffffu;

  {
    int s = g_off_row[node] + g_part_row[node >> 10];
    int cnt = g_cnt_row[node];
    for (int bse = 0; bse < cnt; bse += 32) {
      int n = min(32, cnt - bse);
      int idx = (lane < n) ? g_sorted_col[s + bse + lane] : 0;
      int j = 0;
      for (; j + 4 <= n; j += 4) {
        int i0 = __shfl_sync(FULL, idx, j);
        int i1 = __shfl_sync(FULL, idx, j + 1);
        int i2 = __shfl_sync(FULL, idx, j + 2);
        int i3 = __shfl_sync(FULL, idx, j + 3);
        uint2 v0 = ((const uint2*)g_y_src)[(long long)i0 * 32 + lane];
        uint2 v1 = ((const uint2*)g_y_src)[(long long)i1 * 32 + lane];
        uint2 v2 = ((const uint2*)g_y_src)[(long long)i2 * 32 + lane];
        uint2 v3 = ((const uint2*)g_y_src)[(long long)i3 * 32 + lane];
        acc_row(accf, v0); acc_row(accf, v1); acc_row(accf, v2); acc_row(accf, v3);
      }
      for (; j < n; j++) {
        int i0 = __shfl_sync(FULL, idx, j);
        uint2 v0 = ((const uint2*)g_y_src)[(long long)i0 * 32 + lane];
        acc_row(accf, v0);
      }
    }
  }
  {
    int s = g_off_col[node] + g_part_col[node >> 10];
    int cnt = g_cnt_col[node];
    for (int bse = 0; bse < cnt; bse += 32) {
      int n = min(32, cnt - bse);
      int idx = (lane < n) ? g_sorted_row[s + bse + lane] : 0;
      int j = 0;
      for (; j + 4 <= n; j += 4) {
        int i0 = __shfl_sync(FULL, idx, j);
        int i1 = __shfl_sync(FULL, idx, j + 1);
        int i2 = __shfl_sync(FULL, idx, j + 2);
        int i3 = __shfl_sync(FULL, idx, j + 3);
        uint2 v0 = ((const uint2*)g_y_dst)[(long long)i0 * 32 + lane];
        uint2 v1 = ((const uint2*)g_y_dst)[(long long)i1 * 32 + lane];
        uint2 v2 = ((const uint2*)g_y_dst)[(long long)i2 * 32 + lane];
        uint2 v3 = ((const uint2*)g_y_dst)[(long long)i3 * 32 + lane];
        acc_row(accb, v0); acc_row(accb, v1); acc_row(accb, v2); acc_row(accb, v3);
      }
      for (; j < n; j++) {
        int i0 = __shfl_sync(FULL, idx, j);
        uint2 v0 = ((const uint2*)g_y_dst)[(long long)i0 * 32 + lane];
        acc_row(accb, v0);
      }
    }
  }

  float dout = g_dinv_out[node];
  float di   = g_dinv_in[node];
  int bidx = lane * 4;
  float4 o;
  o.x = ALPHA * b_src[bidx+0] + (1.f-ALPHA) * b_dst[bidx+0] + dout * accf.x + di * accb.x;
  o.y = ALPHA * b_src[bidx+1] + (1.f-ALPHA) * b_dst[bidx+1] + dout * accf.y + di * accb.y;
  o.z = ALPHA * b_src[bidx+2] + (1.f-ALPHA) * b_dst[bidx+2] + dout * accf.z + di * accb.z;
  o.w = ALPHA * b_src[bidx+3] + (1.f-ALPHA) * b_dst[bidx+3] + dout * accf.w + di * accb.w;
  ((float4*)(out + (long long)node * D))[lane] = o;
}

// -------- launch: R11 fork-join (scan+build overlap transform) --------
extern "C" void kernel_launch(void* const* d_in, const int* in_sizes, int n_in,
                              void* d_out, int out_size) {
  const float* x     = (const float*)d_in[0];
  const void*  ei    = d_in[1];
  const float* W_src = (const float*)d_in[2];
  const float* b_src = (const float*)d_in[3];
  const float* W_dst = (const float*)d_in[4];
  const float* b_dst = (const float*)d_in[5];
  float* out = (float*)d_out;

  cudaStream_t s2;
  cudaStreamCreateWithFlags(&s2, cudaStreamNonBlocking);
  cudaEvent_t evFork, evJoin;
  cudaEventCreateWithFlags(&evFork, cudaEventDisableTiming);
  cudaEventCreateWithFlags(&evJoin, cudaEventDisableTiming);

  k_prep<<<(N_NODES + 255) / 256, 256>>>(ei);
  k_hist<<<(N_EDGES + 255) / 256, 256>>>(ei);

  cudaEventRecord(evFork, 0);
  cudaStreamWaitEvent(s2, evFork, 0);
  k_scan_blocks<<<SCAN_NB, SCAN_B, 0, s2>>>();
  k_scan_tops<<<1, 128, 0, s2>>>();
  k_build<<<(N_EDGES + 255) / 256, 256, 0, s2>>>(ei);
  cudaEventRecord(evJoin, s2);

  size_t smem_bytes = (size_t)(128 * NSTR + 2 * TILE_NODES * XSTR) * sizeof(float);
  cudaFuncSetAttribute(k_transform, cudaFuncAttributeMaxDynamicSharedMemorySize,
                       (int)smem_bytes);
  k_transform<<<152, 256, smem_bytes>>>(x, W_src, W_dst);

  cudaStreamWaitEvent(0, evJoin, 0);
  k_gather<<<(N_NODES * 32 + 255) / 256, 256>>>(out, b_src, b_dst);
}